// round 14
// baseline (speedup 1.0000x reference)
#include <cuda_runtime.h>
#include <cuda_bf16.h>
#include <math.h>
#include <stdint.h>

// Batched log(M) for SPD 64x64 matrices, spectrum in [1, 6]:
// degree-8 Chebyshev poly of log in T = (M - 3.5 I)/2.5, PS s=2 (4 matmuls),
// mma.sync m16n8k16 bf16 (HMMA), 2-way truncation split, 3-term products.
// Warp owns 16 rows x 64 cols; AC flows register->register. 32KB smem/CTA:
// the T bf16 tiles are REUSED for T2 (extra barrier between step-0 mm and
// epilogue-0), T epilogue values in a fragment-layout f32 buffer. 5 CTAs/SM
// (launch_bounds(128,5), ~102 regs). Step-0 aliases B-frags to A-frags for
// nj == warp (A rows == that B group's rows; identical ldsm register layout).

constexpr int DEG = 8;
struct Poly { float a[DEG + 1]; };

constexpr int TILE = 8192;            // one 64x64 bf16 tile
constexpr int SMEM_TOT = 4 * TILE;    // [T h/l -> T2 h/l] | Tfrag f32 (16KB)

__device__ __forceinline__ uint32_t smem_u32(const void* p) {
    uint32_t a;
    asm("{ .reg .u64 t; cvta.to.shared.u64 t, %1; cvt.u32.u64 %0, t; }"
        : "=r"(a) : "l"(p));
    return a;
}
__device__ __forceinline__ void sts32(uint32_t addr, uint32_t v) {
    asm volatile("st.shared.b32 [%0], %1;" :: "r"(addr), "r"(v));
}
__device__ __forceinline__ uint32_t lds32(uint32_t addr) {
    uint32_t v;
    asm volatile("ld.shared.b32 %0, [%1];" : "=r"(v) : "r"(addr));
    return v;
}
__device__ __forceinline__ void sts64(uint32_t addr, float x, float y) {
    asm volatile("st.shared.v2.f32 [%0], {%1,%2};" :: "r"(addr), "f"(x), "f"(y));
}
__device__ __forceinline__ float2 lds64f(uint32_t addr) {
    float2 v;
    asm volatile("ld.shared.v2.f32 {%0,%1}, [%2];" : "=f"(v.x), "=f"(v.y) : "r"(addr));
    return v;
}
__device__ __forceinline__ uint32_t packbf(float lo, float hi) {
    uint32_t r;
    asm("cvt.rn.bf16x2.f32 %0, %1, %2;" : "=r"(r) : "f"(hi), "f"(lo));
    return r;
}
__device__ __forceinline__ float2 unpackbf(uint32_t u) {
    const __nv_bfloat162 b = *reinterpret_cast<const __nv_bfloat162*>(&u);
    return make_float2(__bfloat162float(b.x), __bfloat162float(b.y));
}
// truncation split of a pair: h = [x0.hi16|x1.hi16] (x0 low), l = residuals
__device__ __forceinline__ void split_pair(float x0, float x1,
                                           uint32_t& h01, uint32_t& l01) {
    const uint32_t u0 = __float_as_uint(x0), u1 = __float_as_uint(x1);
    asm("prmt.b32 %0, %1, %2, 0x7632;" : "=r"(h01) : "r"(u0), "r"(u1));
    const float l0 = x0 - __uint_as_float(u0 & 0xFFFF0000u);
    const float l1 = x1 - __uint_as_float(u1 & 0xFFFF0000u);
    l01 = packbf(l0, l1);
}
__device__ __forceinline__ void ldsm4(uint32_t r[4], uint32_t addr) {
    asm volatile("ldmatrix.sync.aligned.m8n8.x4.shared.b16 {%0,%1,%2,%3}, [%4];"
                 : "=r"(r[0]), "=r"(r[1]), "=r"(r[2]), "=r"(r[3]) : "r"(addr));
}
__device__ __forceinline__ void mma16816(float c[4], const uint32_t a[4],
                                         uint32_t b0, uint32_t b1) {
    asm volatile(
        "mma.sync.aligned.m16n8k16.row.col.f32.bf16.bf16.f32 "
        "{%0,%1,%2,%3}, {%4,%5,%6,%7}, {%8,%9}, {%0,%1,%2,%3};"
        : "+f"(c[0]), "+f"(c[1]), "+f"(c[2]), "+f"(c[3])
        : "r"(a[0]), "r"(a[1]), "r"(a[2]), "r"(a[3]), "r"(b0), "r"(b1));
}

// 6 MMAs for one n16 group (3 split terms x 2 n8 subs)
__device__ __forceinline__ void mma_nj(float acc[8][4], int nj,
                                       const uint32_t ah[4], const uint32_t al[4],
                                       const uint32_t bh[4], const uint32_t bl[4]) {
#pragma unroll
    for (int sub = 0; sub < 2; ++sub) {
        float* c = acc[nj * 2 + sub];
        mma16816(c, ah, bh[sub], bh[sub + 2]);   // Ah*Bh
        mma16816(c, ah, bl[sub], bl[sub + 2]);   // Ah*Bl
        mma16816(c, al, bh[sub], bh[sub + 2]);   // Al*Bh
    }
}

// One k16 chunk of C(16x64) += A(16x16) * Y^T (B-frags from smem for all nj)
__device__ __forceinline__ void mma_k16(float acc[8][4],
                                        const uint32_t ah[4], const uint32_t al[4],
                                        uint32_t ybase) {
#pragma unroll
    for (int nj = 0; nj < 4; ++nj) {
        uint32_t bh[4], bl[4];
        ldsm4(bh, ybase + nj * 2048);
        ldsm4(bl, ybase + nj * 2048 + TILE);
        mma_nj(acc, nj, ah, al, bh, bl);
    }
}

__global__ __launch_bounds__(128, 5)
void logm_hmma_kernel(const float* __restrict__ gin,
                      float* __restrict__ gout,
                      Poly P) {
    extern __shared__ char smc[];
    const uint32_t sb  = smem_u32(smc);
    const uint32_t bT  = sb;              // T bf16 h/l; becomes T2 h/l after
    const uint32_t bT2 = sb;              //   the mid-step-0 barrier
    const uint32_t bTf = sb + 2 * TILE;   // T f32 fragment layout [pos][tid]

    const int tid  = threadIdx.x;
    const int warp = tid >> 5;
    const int lane = tid & 31;
    const int row0 = warp * 16;

    // ---- prologue: T = (M - 3.5 I)/2.5; truncation-split into bT
    {
        const int pr = tid >> 1, ph = tid & 1;
        const float* gp = gin + (size_t)blockIdx.x * 4096 + pr * 64 + ph * 32;
        float v[32];
#pragma unroll
        for (int j = 0; j < 32; j += 4) {
            const float4 t4 = *reinterpret_cast<const float4*>(gp + j);
            v[j] = t4.x; v[j + 1] = t4.y; v[j + 2] = t4.z; v[j + 3] = t4.w;
        }
        const float inv_beta = 1.0f / 2.5f, alpha = 3.5f;
#pragma unroll
        for (int j = 0; j < 32; ++j)
            v[j] = (v[j] - ((ph * 32 + j == pr) ? alpha : 0.0f)) * inv_beta;

        const uint32_t pmsk = (uint32_t)((pr & 7) << 4);
#pragma unroll
        for (int j = 0; j < 16; ++j) {
            const uint32_t off = ((uint32_t)(pr * 128 + ph * 64 + 4 * j)) ^ pmsk;
            uint32_t h01, l01;
            split_pair(v[2 * j], v[2 * j + 1], h01, l01);
            sts32(bT + off, h01);
            sts32(bT + TILE + off, l01);
        }
    }
    __syncthreads();                       // barrier 1: T visible

    // ---- per-thread constant geometry
    const int la = lane & 15, lc = lane >> 4;
    const uint32_t msk = (uint32_t)((la & 7) << 4);
    const uint32_t rA  = (uint32_t)((row0 + la) * 128 + lc * 16);
    const uint32_t rY  = (uint32_t)(la * 128 + lc * 16);
    const int er = lane >> 2, ec = (lane & 3) * 2;
    const uint32_t mskE = (uint32_t)(er << 4);
    const uint32_t rE0  = (uint32_t)((row0 + er) * 128 + ec * 2);
    const uint32_t rTf  = bTf + (uint32_t)(tid * 8);   // own fragment column

    // diag masks over pos = ni*2+hf
    uint32_t dm0 = 0, dm1 = 0;
#pragma unroll
    for (int ni = 0; ni < 8; ++ni)
#pragma unroll
        for (int hf = 0; hf < 2; ++hf) {
            const int gr = row0 + er + hf * 8;
            const int gc = ni * 8 + ec;
            if (gr == gc)     dm0 |= 1u << (ni * 2 + hf);
            if (gr == gc + 1) dm1 |= 1u << (ni * 2 + hf);
        }

    // ---- one-time gather: T fragments -> bTf[pos][tid] (thread-private slots)
#pragma unroll
    for (int ni = 0; ni < 8; ++ni)
#pragma unroll
        for (int hf = 0; hf < 2; ++hf) {
            const uint32_t rel = (rE0 + (uint32_t)(ni * 16 + hf * 1024)) ^ mskE;
            const float2 th = unpackbf(lds32(bT + rel));
            const float2 tl = unpackbf(lds32(bT + TILE + rel));
            sts64(rTf + (uint32_t)((ni * 2 + hf) * 1024), th.x + tl.x, th.y + tl.y);
        }

    float    acc[8][4];
    uint32_t fh[16], fl[16];   // A-fragments of own AC rows (pos = ni*2+hf)

    // ================= step 0: X = Y = T =================
#pragma unroll
    for (int t = 0; t < 8; ++t)
#pragma unroll
        for (int e = 0; e < 4; ++e) acc[t][e] = 0.0f;
#pragma unroll
    for (int ks = 0; ks < 4; ++ks) {
        const uint32_t kb = (uint32_t)(ks * 32);
        const uint32_t xa = bT + ((rA + kb) ^ msk);
        const uint32_t ya = bT + ((rY + kb) ^ msk);
        uint32_t ah[4], al[4];
        ldsm4(ah, xa);
        ldsm4(al, xa + TILE);
#pragma unroll
        for (int nj = 0; nj < 4; ++nj) {
            if (nj == warp) {
                // B rows of this group == A rows; identical ldsm layout
                mma_nj(acc, nj, ah, al, ah, al);
            } else {
                uint32_t bh[4], bl[4];
                ldsm4(bh, ya + nj * 2048);
                ldsm4(bl, ya + nj * 2048 + TILE);
                mma_nj(acc, nj, ah, al, bh, bl);
            }
        }
    }
    __syncthreads();                       // barrier 2: all T reads complete

    // epilogue 0: T2 = D -> bT2 (over T); AC = a8*D + a7*T + a6*I -> frags
    {
        const float cd = P.a[8], c1 = P.a[7], cc0 = P.a[6];
#pragma unroll
        for (int ni = 0; ni < 8; ++ni)
#pragma unroll
            for (int hf = 0; hf < 2; ++hf) {
                const int pos = ni * 2 + hf;
                const uint32_t rel = (rE0 + (uint32_t)(ni * 16 + hf * 1024)) ^ mskE;
                const float d0 = acc[ni][2 * hf];
                const float d1 = acc[ni][2 * hf + 1];
                uint32_t t2h, t2l;                       // raw D IS T2
                split_pair(d0, d1, t2h, t2l);
                sts32(bT2 + rel, t2h);
                sts32(bT2 + TILE + rel, t2l);
                const float2 tf = lds64f(rTf + (uint32_t)(pos * 1024));
                float x0 = cd * d0 + c1 * tf.x;
                float x1 = cd * d1 + c1 * tf.y;
                if ((dm0 >> pos) & 1) x0 += cc0;
                if ((dm1 >> pos) & 1) x1 += cc0;
                split_pair(x0, x1, fh[pos], fl[pos]);
            }
    }
    __syncthreads();                       // barrier 3: T2 visible; then free-run

    // precomputed swizzled T2 chunk bases (reused by all 3 remaining steps)
    uint32_t yb[4];
#pragma unroll
    for (int ks = 0; ks < 4; ++ks)
        yb[ks] = bT2 + ((rY + (uint32_t)(ks * 32)) ^ msk);

    // ================= steps 1..3: acc preloaded with c1*T + cc0*I =========
#pragma unroll
    for (int step = 1; step < 4; ++step) {
        const float c1  = (step == 1) ? P.a[5] : (step == 2) ? P.a[3] : P.a[1];
        const float cc0 = (step == 1) ? P.a[4] : (step == 2) ? P.a[2] : P.a[0];

        // init acc = c1*T + cc0*I  (conflict-free LDS.64 from own fragment col)
#pragma unroll
        for (int ni = 0; ni < 8; ++ni)
#pragma unroll
            for (int hf = 0; hf < 2; ++hf) {
                const int pos = ni * 2 + hf;
                const float2 tf = lds64f(rTf + (uint32_t)(pos * 1024));
                float x0 = c1 * tf.x;
                float x1 = c1 * tf.y;
                if ((dm0 >> pos) & 1) x0 += cc0;
                if ((dm1 >> pos) & 1) x1 += cc0;
                acc[ni][2 * hf]     = x0;
                acc[ni][2 * hf + 1] = x1;
            }

        // mm: AC_new = AC*T2 + acc_init   (A-frags straight from registers)
#pragma unroll
        for (int ks = 0; ks < 4; ++ks)
            mma_k16(acc, &fh[4 * ks], &fl[4 * ks], yb[ks]);

        if (step < 3) {
            // epilogue = split only
#pragma unroll
            for (int pos = 0; pos < 16; ++pos)
                split_pair(acc[pos >> 1][2 * (pos & 1)],
                           acc[pos >> 1][2 * (pos & 1) + 1], fh[pos], fl[pos]);
        } else {
            // final: store to global
#pragma unroll
            for (int ni = 0; ni < 8; ++ni)
#pragma unroll
                for (int hf = 0; hf < 2; ++hf) {
                    const int gr = row0 + er + hf * 8;
                    const int gc = ni * 8 + ec;
                    float2* gp = reinterpret_cast<float2*>(
                        gout + (size_t)blockIdx.x * 4096 + gr * 64 + gc);
                    *gp = make_float2(acc[ni][2 * hf], acc[ni][2 * hf + 1]);
                }
        }
    }
}

extern "C" void kernel_launch(void* const* d_in, const int* in_sizes, int n_in,
                              void* d_out, int out_size) {
    const float* in = (const float*)d_in[0];
    float* out = (float*)d_out;
    const int nmat = in_sizes[0] / 4096;   // 8192 matrices of 64x64

    // Chebyshev coefficients of log on [1,6], converted to monomial basis.
    Poly P;
    {
        const double alpha = 3.5, beta = 2.5;
        const double r = (alpha - sqrt(alpha * alpha - beta * beta)) / beta;
        double c[DEG + 1];
        c[0] = log(alpha / (1.0 + r * r));
        double rk = 1.0;
        for (int k = 1; k <= DEG; ++k) {
            rk *= r;
            c[k] = ((k & 1) ? 2.0 : -2.0) * rk / (double)k;
        }
        double mono[DEG + 1], Tm1[DEG + 1], Tc[DEG + 1], Tn[DEG + 1];
        for (int j = 0; j <= DEG; ++j) { mono[j] = 0; Tm1[j] = 0; Tc[j] = 0; }
        Tm1[0] = 1.0;            // T0
        Tc[1]  = 1.0;            // T1
        for (int j = 0; j <= DEG; ++j) mono[j] = c[0] * Tm1[j] + c[1] * Tc[j];
        for (int k = 2; k <= DEG; ++k) {
            for (int j = 0; j <= DEG; ++j) {
                double t = -Tm1[j];
                if (j > 0) t += 2.0 * Tc[j - 1];
                Tn[j] = t;
            }
            for (int j = 0; j <= DEG; ++j) {
                mono[j] += c[k] * Tn[j];
                Tm1[j] = Tc[j];
                Tc[j]  = Tn[j];
            }
        }
        for (int j = 0; j <= DEG; ++j) P.a[j] = (float)mono[j];
    }

    cudaFuncSetAttribute(logm_hmma_kernel,
                         cudaFuncAttributeMaxDynamicSharedMemorySize, SMEM_TOT);
    logm_hmma_kernel<<<nmat, 128, SMEM_TOT>>>(in, out, P);
}

// round 15
// speedup vs baseline: 1.0001x; 1.0001x over previous
#include <cuda_runtime.h>
#include <cuda_bf16.h>
#include <math.h>
#include <stdint.h>

// Batched log(M) for SPD 64x64 matrices, spectrum in [1, 6]:
// degree-8 Chebyshev poly of log in T = (M - 3.5 I)/2.5, PS s=2 (4 matmuls),
// mma.sync m16n8k16 bf16 (HMMA), 2-way truncation split, 3-term products.
// Warp owns 16 rows x 64 cols; AC flows register->register (C-frag layout ==
// A-frag layout); one barrier after step 0; steps 1-3 barrier-free with acc
// preloaded as c1*T + cc0*I from a fragment-layout f32 buffer (conflict-free
// LDS.64). R15 = R13 + (a) step-0 B-frag alias for nj==warp, (b) Tf gather
// fused into epilogue-0 (no pre-MMA gather phase). 48KB smem, 4 CTAs/SM.

constexpr int DEG = 8;
struct Poly { float a[DEG + 1]; };

constexpr int TILE = 8192;            // one 64x64 bf16 tile
constexpr int SMEM_TOT = 6 * TILE;    // Th,Tl | T2h,T2l | Tfrag f32 (16KB)

__device__ __forceinline__ uint32_t smem_u32(const void* p) {
    uint32_t a;
    asm("{ .reg .u64 t; cvta.to.shared.u64 t, %1; cvt.u32.u64 %0, t; }"
        : "=r"(a) : "l"(p));
    return a;
}
__device__ __forceinline__ void sts32(uint32_t addr, uint32_t v) {
    asm volatile("st.shared.b32 [%0], %1;" :: "r"(addr), "r"(v));
}
__device__ __forceinline__ uint32_t lds32(uint32_t addr) {
    uint32_t v;
    asm volatile("ld.shared.b32 %0, [%1];" : "=r"(v) : "r"(addr));
    return v;
}
__device__ __forceinline__ void sts64(uint32_t addr, float x, float y) {
    asm volatile("st.shared.v2.f32 [%0], {%1,%2};" :: "r"(addr), "f"(x), "f"(y));
}
__device__ __forceinline__ float2 lds64f(uint32_t addr) {
    float2 v;
    asm volatile("ld.shared.v2.f32 {%0,%1}, [%2];" : "=f"(v.x), "=f"(v.y) : "r"(addr));
    return v;
}
__device__ __forceinline__ uint32_t packbf(float lo, float hi) {
    uint32_t r;
    asm("cvt.rn.bf16x2.f32 %0, %1, %2;" : "=r"(r) : "f"(hi), "f"(lo));
    return r;
}
__device__ __forceinline__ float2 unpackbf(uint32_t u) {
    const __nv_bfloat162 b = *reinterpret_cast<const __nv_bfloat162*>(&u);
    return make_float2(__bfloat162float(b.x), __bfloat162float(b.y));
}
// truncation split of a pair: h = [x0.hi16|x1.hi16] (x0 low), l = residuals
__device__ __forceinline__ void split_pair(float x0, float x1,
                                           uint32_t& h01, uint32_t& l01) {
    const uint32_t u0 = __float_as_uint(x0), u1 = __float_as_uint(x1);
    asm("prmt.b32 %0, %1, %2, 0x7632;" : "=r"(h01) : "r"(u0), "r"(u1));
    const float l0 = x0 - __uint_as_float(u0 & 0xFFFF0000u);
    const float l1 = x1 - __uint_as_float(u1 & 0xFFFF0000u);
    l01 = packbf(l0, l1);
}
__device__ __forceinline__ void ldsm4(uint32_t r[4], uint32_t addr) {
    asm volatile("ldmatrix.sync.aligned.m8n8.x4.shared.b16 {%0,%1,%2,%3}, [%4];"
                 : "=r"(r[0]), "=r"(r[1]), "=r"(r[2]), "=r"(r[3]) : "r"(addr));
}
__device__ __forceinline__ void mma16816(float c[4], const uint32_t a[4],
                                         uint32_t b0, uint32_t b1) {
    asm volatile(
        "mma.sync.aligned.m16n8k16.row.col.f32.bf16.bf16.f32 "
        "{%0,%1,%2,%3}, {%4,%5,%6,%7}, {%8,%9}, {%0,%1,%2,%3};"
        : "+f"(c[0]), "+f"(c[1]), "+f"(c[2]), "+f"(c[3])
        : "r"(a[0]), "r"(a[1]), "r"(a[2]), "r"(a[3]), "r"(b0), "r"(b1));
}

// 6 MMAs for one n16 group (3 split terms x 2 n8 subs)
__device__ __forceinline__ void mma_nj(float acc[8][4], int nj,
                                       const uint32_t ah[4], const uint32_t al[4],
                                       const uint32_t bh[4], const uint32_t bl[4]) {
#pragma unroll
    for (int sub = 0; sub < 2; ++sub) {
        float* c = acc[nj * 2 + sub];
        mma16816(c, ah, bh[sub], bh[sub + 2]);   // Ah*Bh
        mma16816(c, ah, bl[sub], bl[sub + 2]);   // Ah*Bl
        mma16816(c, al, bh[sub], bh[sub + 2]);   // Al*Bh
    }
}

// One k16 chunk of C(16x64) += A(16x16) * Y^T (B-frags from smem for all nj;
// ybase pre-swizzled, +nj*2048 preserves the swizzle: row%8 bits unchanged)
__device__ __forceinline__ void mma_k16(float acc[8][4],
                                        const uint32_t ah[4], const uint32_t al[4],
                                        uint32_t ybase) {
#pragma unroll
    for (int nj = 0; nj < 4; ++nj) {
        uint32_t bh[4], bl[4];
        ldsm4(bh, ybase + nj * 2048);
        ldsm4(bl, ybase + nj * 2048 + TILE);
        mma_nj(acc, nj, ah, al, bh, bl);
    }
}

__global__ __launch_bounds__(128, 4)
void logm_hmma_kernel(const float* __restrict__ gin,
                      float* __restrict__ gout,
                      Poly P) {
    extern __shared__ char smc[];
    const uint32_t sb  = smem_u32(smc);
    const uint32_t bT  = sb;              // T bf16 hi (+TILE lo), persistent
    const uint32_t bT2 = sb + 2 * TILE;   // T2 bf16 hi (+TILE lo)
    const uint32_t bTf = sb + 4 * TILE;   // T f32 fragment layout [pos][tid]

    const int tid  = threadIdx.x;
    const int warp = tid >> 5;
    const int lane = tid & 31;
    const int row0 = warp * 16;

    // ---- prologue: T = (M - 3.5 I)/2.5; truncation-split into bT
    {
        const int pr = tid >> 1, ph = tid & 1;
        const float* gp = gin + (size_t)blockIdx.x * 4096 + pr * 64 + ph * 32;
        float v[32];
#pragma unroll
        for (int j = 0; j < 32; j += 4) {
            const float4 t4 = *reinterpret_cast<const float4*>(gp + j);
            v[j] = t4.x; v[j + 1] = t4.y; v[j + 2] = t4.z; v[j + 3] = t4.w;
        }
        const float inv_beta = 1.0f / 2.5f, alpha = 3.5f;
#pragma unroll
        for (int j = 0; j < 32; ++j)
            v[j] = (v[j] - ((ph * 32 + j == pr) ? alpha : 0.0f)) * inv_beta;

        const uint32_t pmsk = (uint32_t)((pr & 7) << 4);
#pragma unroll
        for (int j = 0; j < 16; ++j) {
            const uint32_t off = ((uint32_t)(pr * 128 + ph * 64 + 4 * j)) ^ pmsk;
            uint32_t h01, l01;
            split_pair(v[2 * j], v[2 * j + 1], h01, l01);
            sts32(bT + off, h01);
            sts32(bT + TILE + off, l01);
        }
    }
    __syncthreads();

    // ---- per-thread constant geometry
    const int la = lane & 15, lc = lane >> 4;
    const uint32_t msk = (uint32_t)((la & 7) << 4);
    const uint32_t rA  = (uint32_t)((row0 + la) * 128 + lc * 16);
    const uint32_t rY  = (uint32_t)(la * 128 + lc * 16);
    const int er = lane >> 2, ec = (lane & 3) * 2;
    const uint32_t mskE = (uint32_t)(er << 4);
    const uint32_t rE0  = (uint32_t)((row0 + er) * 128 + ec * 2);
    const uint32_t rTf  = bTf + (uint32_t)(tid * 8);   // own fragment column

    // diag masks over pos = ni*2+hf
    uint32_t dm0 = 0, dm1 = 0;
#pragma unroll
    for (int ni = 0; ni < 8; ++ni)
#pragma unroll
        for (int hf = 0; hf < 2; ++hf) {
            const int gr = row0 + er + hf * 8;
            const int gc = ni * 8 + ec;
            if (gr == gc)     dm0 |= 1u << (ni * 2 + hf);
            if (gr == gc + 1) dm1 |= 1u << (ni * 2 + hf);
        }

    float    acc[8][4];
    uint32_t fh[16], fl[16];   // A-fragments of own AC rows (pos = ni*2+hf)

    // ================= step 0: X = Y = T (nj==warp B-frags alias A-frags) ====
#pragma unroll
    for (int t = 0; t < 8; ++t)
#pragma unroll
        for (int e = 0; e < 4; ++e) acc[t][e] = 0.0f;
#pragma unroll
    for (int ks = 0; ks < 4; ++ks) {
        const uint32_t kb = (uint32_t)(ks * 32);
        const uint32_t xa = bT + ((rA + kb) ^ msk);
        const uint32_t ya = bT + ((rY + kb) ^ msk);
        uint32_t ah[4], al[4];
        ldsm4(ah, xa);
        ldsm4(al, xa + TILE);
#pragma unroll
        for (int nj = 0; nj < 4; ++nj) {
            if (nj == warp) {
                // B rows of this group == A rows; identical ldsm layout
                mma_nj(acc, nj, ah, al, ah, al);
            } else {
                uint32_t bh[4], bl[4];
                ldsm4(bh, ya + nj * 2048);
                ldsm4(bl, ya + nj * 2048 + TILE);
                mma_nj(acc, nj, ah, al, bh, bl);
            }
        }
    }

    // epilogue 0 (fused Tf gather): T2 = D -> bT2; tf from bT directly;
    // Tf[pos][tid] written for steps 1-3; AC = a8*D + a7*T + a6*I -> frags.
    {
        const float cd = P.a[8], c1 = P.a[7], cc0 = P.a[6];
#pragma unroll
        for (int ni = 0; ni < 8; ++ni)
#pragma unroll
            for (int hf = 0; hf < 2; ++hf) {
                const int pos = ni * 2 + hf;
                const uint32_t rel = (rE0 + (uint32_t)(ni * 16 + hf * 1024)) ^ mskE;
                const float d0 = acc[ni][2 * hf];
                const float d1 = acc[ni][2 * hf + 1];
                uint32_t t2h, t2l;                       // raw D IS T2
                split_pair(d0, d1, t2h, t2l);
                sts32(bT2 + rel, t2h);
                sts32(bT2 + TILE + rel, t2l);
                const float2 th = unpackbf(lds32(bT + rel));
                const float2 tl = unpackbf(lds32(bT + TILE + rel));
                const float tfx = th.x + tl.x, tfy = th.y + tl.y;
                sts64(rTf + (uint32_t)(pos * 1024), tfx, tfy);
                float x0 = cd * d0 + c1 * tfx;
                float x1 = cd * d1 + c1 * tfy;
                if ((dm0 >> pos) & 1) x0 += cc0;
                if ((dm1 >> pos) & 1) x1 += cc0;
                split_pair(x0, x1, fh[pos], fl[pos]);
            }
    }
    __syncthreads();   // T2 (and Tf) visible; steps 1-3 barrier-free

    // precomputed swizzled T2 chunk bases (reused by all 3 remaining steps)
    uint32_t yb[4];
#pragma unroll
    for (int ks = 0; ks < 4; ++ks)
        yb[ks] = bT2 + ((rY + (uint32_t)(ks * 32)) ^ msk);

    // ================= steps 1..3: acc preloaded with c1*T + cc0*I =========
#pragma unroll
    for (int step = 1; step < 4; ++step) {
        const float c1  = (step == 1) ? P.a[5] : (step == 2) ? P.a[3] : P.a[1];
        const float cc0 = (step == 1) ? P.a[4] : (step == 2) ? P.a[2] : P.a[0];

        // init acc = c1*T + cc0*I  (conflict-free LDS.64 from own fragment col)
#pragma unroll
        for (int ni = 0; ni < 8; ++ni)
#pragma unroll
            for (int hf = 0; hf < 2; ++hf) {
                const int pos = ni * 2 + hf;
                const float2 tf = lds64f(rTf + (uint32_t)(pos * 1024));
                float x0 = c1 * tf.x;
                float x1 = c1 * tf.y;
                if ((dm0 >> pos) & 1) x0 += cc0;
                if ((dm1 >> pos) & 1) x1 += cc0;
                acc[ni][2 * hf]     = x0;
                acc[ni][2 * hf + 1] = x1;
            }

        // mm: AC_new = AC*T2 + acc_init   (A-frags straight from registers)
#pragma unroll
        for (int ks = 0; ks < 4; ++ks)
            mma_k16(acc, &fh[4 * ks], &fl[4 * ks], yb[ks]);

        if (step < 3) {
            // epilogue = split only
#pragma unroll
            for (int pos = 0; pos < 16; ++pos)
                split_pair(acc[pos >> 1][2 * (pos & 1)],
                           acc[pos >> 1][2 * (pos & 1) + 1], fh[pos], fl[pos]);
        } else {
            // final: store to global
#pragma unroll
            for (int ni = 0; ni < 8; ++ni)
#pragma unroll
                for (int hf = 0; hf < 2; ++hf) {
                    const int gr = row0 + er + hf * 8;
                    const int gc = ni * 8 + ec;
                    float2* gp = reinterpret_cast<float2*>(
                        gout + (size_t)blockIdx.x * 4096 + gr * 64 + gc);
                    *gp = make_float2(acc[ni][2 * hf], acc[ni][2 * hf + 1]);
                }
        }
    }
}

extern "C" void kernel_launch(void* const* d_in, const int* in_sizes, int n_in,
                              void* d_out, int out_size) {
    const float* in = (const float*)d_in[0];
    float* out = (float*)d_out;
    const int nmat = in_sizes[0] / 4096;   // 8192 matrices of 64x64

    // Chebyshev coefficients of log on [1,6], converted to monomial basis.
    Poly P;
    {
        const double alpha = 3.5, beta = 2.5;
        const double r = (alpha - sqrt(alpha * alpha - beta * beta)) / beta;
        double c[DEG + 1];
        c[0] = log(alpha / (1.0 + r * r));
        double rk = 1.0;
        for (int k = 1; k <= DEG; ++k) {
            rk *= r;
            c[k] = ((k & 1) ? 2.0 : -2.0) * rk / (double)k;
        }
        double mono[DEG + 1], Tm1[DEG + 1], Tc[DEG + 1], Tn[DEG + 1];
        for (int j = 0; j <= DEG; ++j) { mono[j] = 0; Tm1[j] = 0; Tc[j] = 0; }
        Tm1[0] = 1.0;            // T0
        Tc[1]  = 1.0;            // T1
        for (int j = 0; j <= DEG; ++j) mono[j] = c[0] * Tm1[j] + c[1] * Tc[j];
        for (int k = 2; k <= DEG; ++k) {
            for (int j = 0; j <= DEG; ++j) {
                double t = -Tm1[j];
                if (j > 0) t += 2.0 * Tc[j - 1];
                Tn[j] = t;
            }
            for (int j = 0; j <= DEG; ++j) {
                mono[j] += c[k] * Tn[j];
                Tm1[j] = Tc[j];
                Tc[j]  = Tn[j];
            }
        }
        for (int j = 0; j <= DEG; ++j) P.a[j] = (float)mono[j];
    }

    cudaFuncSetAttribute(logm_hmma_kernel,
                         cudaFuncAttributeMaxDynamicSharedMemorySize, SMEM_TOT);
    logm_hmma_kernel<<<nmat, 128, SMEM_TOT>>>(in, out, P);
}

// round 16
// speedup vs baseline: 1.6752x; 1.6750x over previous
#include <cuda_runtime.h>
#include <cuda_bf16.h>
#include <math.h>
#include <stdint.h>

// Batched log(M) for SPD 64x64 matrices, spectrum in [1, 6]:
// degree-8 Chebyshev poly of log in T = (M - 3.5 I)/2.5, PS s=2 (4 matmuls),
// mma.sync m16n8k16 bf16 (HMMA), 2-way truncation split, 3-term products.
// Warp owns 16 rows x 64 cols; AC flows register->register; one barrier after
// step 0; steps 1-3 barrier-free with acc preloaded as c1*T + cc0*I from a
// fragment-layout f32 buffer. R16 = R13 exactly, plus software-pipelined
// (one-ahead) B-fragment ldsm in the steps-1-3 matmuls.

constexpr int DEG = 8;
struct Poly { float a[DEG + 1]; };

constexpr int TILE = 8192;            // one 64x64 bf16 tile
constexpr int SMEM_TOT = 6 * TILE;    // Th,Tl | T2h,T2l | Tfrag f32 (16KB)

__device__ __forceinline__ uint32_t smem_u32(const void* p) {
    uint32_t a;
    asm("{ .reg .u64 t; cvta.to.shared.u64 t, %1; cvt.u32.u64 %0, t; }"
        : "=r"(a) : "l"(p));
    return a;
}
__device__ __forceinline__ void sts32(uint32_t addr, uint32_t v) {
    asm volatile("st.shared.b32 [%0], %1;" :: "r"(addr), "r"(v));
}
__device__ __forceinline__ uint32_t lds32(uint32_t addr) {
    uint32_t v;
    asm volatile("ld.shared.b32 %0, [%1];" : "=r"(v) : "r"(addr));
    return v;
}
__device__ __forceinline__ void sts64(uint32_t addr, float x, float y) {
    asm volatile("st.shared.v2.f32 [%0], {%1,%2};" :: "r"(addr), "f"(x), "f"(y));
}
__device__ __forceinline__ float2 lds64f(uint32_t addr) {
    float2 v;
    asm volatile("ld.shared.v2.f32 {%0,%1}, [%2];" : "=f"(v.x), "=f"(v.y) : "r"(addr));
    return v;
}
__device__ __forceinline__ uint32_t packbf(float lo, float hi) {
    uint32_t r;
    asm("cvt.rn.bf16x2.f32 %0, %1, %2;" : "=r"(r) : "f"(hi), "f"(lo));
    return r;
}
__device__ __forceinline__ float2 unpackbf(uint32_t u) {
    const __nv_bfloat162 b = *reinterpret_cast<const __nv_bfloat162*>(&u);
    return make_float2(__bfloat162float(b.x), __bfloat162float(b.y));
}
// truncation split of a pair: h = [x0.hi16|x1.hi16] (x0 low), l = residuals
__device__ __forceinline__ void split_pair(float x0, float x1,
                                           uint32_t& h01, uint32_t& l01) {
    const uint32_t u0 = __float_as_uint(x0), u1 = __float_as_uint(x1);
    asm("prmt.b32 %0, %1, %2, 0x7632;" : "=r"(h01) : "r"(u0), "r"(u1));
    const float l0 = x0 - __uint_as_float(u0 & 0xFFFF0000u);
    const float l1 = x1 - __uint_as_float(u1 & 0xFFFF0000u);
    l01 = packbf(l0, l1);
}
__device__ __forceinline__ void ldsm4(uint32_t r[4], uint32_t addr) {
    asm volatile("ldmatrix.sync.aligned.m8n8.x4.shared.b16 {%0,%1,%2,%3}, [%4];"
                 : "=r"(r[0]), "=r"(r[1]), "=r"(r[2]), "=r"(r[3]) : "r"(addr));
}
__device__ __forceinline__ void mma16816(float c[4], const uint32_t a[4],
                                         uint32_t b0, uint32_t b1) {
    asm volatile(
        "mma.sync.aligned.m16n8k16.row.col.f32.bf16.bf16.f32 "
        "{%0,%1,%2,%3}, {%4,%5,%6,%7}, {%8,%9}, {%0,%1,%2,%3};"
        : "+f"(c[0]), "+f"(c[1]), "+f"(c[2]), "+f"(c[3])
        : "r"(a[0]), "r"(a[1]), "r"(a[2]), "r"(a[3]), "r"(b0), "r"(b1));
}

// 6 MMAs for one n16 group (3 split terms x 2 n8 subs)
__device__ __forceinline__ void mma_nj(float acc[8][4], int nj,
                                       const uint32_t ah[4], const uint32_t al[4],
                                       const uint32_t bh[4], const uint32_t bl[4]) {
#pragma unroll
    for (int sub = 0; sub < 2; ++sub) {
        float* c = acc[nj * 2 + sub];
        mma16816(c, ah, bh[sub], bh[sub + 2]);   // Ah*Bh
        mma16816(c, ah, bl[sub], bl[sub + 2]);   // Ah*Bl
        mma16816(c, al, bh[sub], bh[sub + 2]);   // Al*Bh
    }
}

// One k16 chunk of C(16x64) += A(16x16) * Y^T (B-frags from smem for all nj;
// ybase pre-swizzled, +nj*2048 preserves the swizzle: row%8 bits unchanged)
__device__ __forceinline__ void mma_k16(float acc[8][4],
                                        const uint32_t ah[4], const uint32_t al[4],
                                        uint32_t ybase) {
#pragma unroll
    for (int nj = 0; nj < 4; ++nj) {
        uint32_t bh[4], bl[4];
        ldsm4(bh, ybase + nj * 2048);
        ldsm4(bl, ybase + nj * 2048 + TILE);
        mma_nj(acc, nj, ah, al, bh, bl);
    }
}

__global__ __launch_bounds__(128, 4)
void logm_hmma_kernel(const float* __restrict__ gin,
                      float* __restrict__ gout,
                      Poly P) {
    extern __shared__ char smc[];
    const uint32_t sb  = smem_u32(smc);
    const uint32_t bT  = sb;              // T bf16 hi (+TILE lo), persistent
    const uint32_t bT2 = sb + 2 * TILE;   // T2 bf16 hi (+TILE lo)
    const uint32_t bTf = sb + 4 * TILE;   // T f32 fragment layout [pos][tid]

    const int tid  = threadIdx.x;
    const int warp = tid >> 5;
    const int lane = tid & 31;
    const int row0 = warp * 16;

    // ---- prologue: T = (M - 3.5 I)/2.5; truncation-split into bT
    {
        const int pr = tid >> 1, ph = tid & 1;
        const float* gp = gin + (size_t)blockIdx.x * 4096 + pr * 64 + ph * 32;
        float v[32];
#pragma unroll
        for (int j = 0; j < 32; j += 4) {
            const float4 t4 = *reinterpret_cast<const float4*>(gp + j);
            v[j] = t4.x; v[j + 1] = t4.y; v[j + 2] = t4.z; v[j + 3] = t4.w;
        }
        const float inv_beta = 1.0f / 2.5f, alpha = 3.5f;
#pragma unroll
        for (int j = 0; j < 32; ++j)
            v[j] = (v[j] - ((ph * 32 + j == pr) ? alpha : 0.0f)) * inv_beta;

        const uint32_t pmsk = (uint32_t)((pr & 7) << 4);
#pragma unroll
        for (int j = 0; j < 16; ++j) {
            const uint32_t off = ((uint32_t)(pr * 128 + ph * 64 + 4 * j)) ^ pmsk;
            uint32_t h01, l01;
            split_pair(v[2 * j], v[2 * j + 1], h01, l01);
            sts32(bT + off, h01);
            sts32(bT + TILE + off, l01);
        }
    }
    __syncthreads();

    // ---- per-thread constant geometry
    const int la = lane & 15, lc = lane >> 4;
    const uint32_t msk = (uint32_t)((la & 7) << 4);
    const uint32_t rA  = (uint32_t)((row0 + la) * 128 + lc * 16);
    const uint32_t rY  = (uint32_t)(la * 128 + lc * 16);
    const int er = lane >> 2, ec = (lane & 3) * 2;
    const uint32_t mskE = (uint32_t)(er << 4);
    const uint32_t rE0  = (uint32_t)((row0 + er) * 128 + ec * 2);
    const uint32_t rTf  = bTf + (uint32_t)(tid * 8);   // own fragment column

    // diag masks over pos = ni*2+hf
    uint32_t dm0 = 0, dm1 = 0;
#pragma unroll
    for (int ni = 0; ni < 8; ++ni)
#pragma unroll
        for (int hf = 0; hf < 2; ++hf) {
            const int gr = row0 + er + hf * 8;
            const int gc = ni * 8 + ec;
            if (gr == gc)     dm0 |= 1u << (ni * 2 + hf);
            if (gr == gc + 1) dm1 |= 1u << (ni * 2 + hf);
        }

    // ---- one-time gather: T fragments -> bTf[pos][tid] (thread-private slots)
#pragma unroll
    for (int ni = 0; ni < 8; ++ni)
#pragma unroll
        for (int hf = 0; hf < 2; ++hf) {
            const uint32_t rel = (rE0 + (uint32_t)(ni * 16 + hf * 1024)) ^ mskE;
            const float2 th = unpackbf(lds32(bT + rel));
            const float2 tl = unpackbf(lds32(bT + TILE + rel));
            sts64(rTf + (uint32_t)((ni * 2 + hf) * 1024), th.x + tl.x, th.y + tl.y);
        }

    float    acc[8][4];
    uint32_t fh[16], fl[16];   // A-fragments of own AC rows (pos = ni*2+hf)

    // ================= step 0: X = Y = T (exact R13 structure) ==============
#pragma unroll
    for (int t = 0; t < 8; ++t)
#pragma unroll
        for (int e = 0; e < 4; ++e) acc[t][e] = 0.0f;
#pragma unroll
    for (int ks = 0; ks < 4; ++ks) {
        const uint32_t kb = (uint32_t)(ks * 32);
        const uint32_t xa = bT + ((rA + kb) ^ msk);
        uint32_t ah[4], al[4];
        ldsm4(ah, xa);
        ldsm4(al, xa + TILE);
        mma_k16(acc, ah, al, bT + ((rY + kb) ^ msk));
    }
    {
        const float cd = P.a[8], c1 = P.a[7], cc0 = P.a[6];
#pragma unroll
        for (int ni = 0; ni < 8; ++ni)
#pragma unroll
            for (int hf = 0; hf < 2; ++hf) {
                const int pos = ni * 2 + hf;
                const uint32_t rel = (rE0 + (uint32_t)(ni * 16 + hf * 1024)) ^ mskE;
                const float d0 = acc[ni][2 * hf];
                const float d1 = acc[ni][2 * hf + 1];
                uint32_t t2h, t2l;                       // raw D IS T2
                split_pair(d0, d1, t2h, t2l);
                sts32(bT2 + rel, t2h);
                sts32(bT2 + TILE + rel, t2l);
                const float2 tf = lds64f(rTf + (uint32_t)(pos * 1024));
                float x0 = cd * d0 + c1 * tf.x;
                float x1 = cd * d1 + c1 * tf.y;
                if ((dm0 >> pos) & 1) x0 += cc0;
                if ((dm1 >> pos) & 1) x1 += cc0;
                split_pair(x0, x1, fh[pos], fl[pos]);
            }
    }
    __syncthreads();   // T2 visible; steps 1-3 barrier-free

    // precomputed swizzled T2 chunk bases (reused by all 3 remaining steps)
    uint32_t yb[4];
#pragma unroll
    for (int ks = 0; ks < 4; ++ks)
        yb[ks] = bT2 + ((rY + (uint32_t)(ks * 32)) ^ msk);

    // ================= steps 1..3: acc preloaded with c1*T + cc0*I =========
#pragma unroll
    for (int step = 1; step < 4; ++step) {
        const float c1  = (step == 1) ? P.a[5] : (step == 2) ? P.a[3] : P.a[1];
        const float cc0 = (step == 1) ? P.a[4] : (step == 2) ? P.a[2] : P.a[0];

        // init acc = c1*T + cc0*I  (conflict-free LDS.64 from own fragment col)
#pragma unroll
        for (int ni = 0; ni < 8; ++ni)
#pragma unroll
            for (int hf = 0; hf < 2; ++hf) {
                const int pos = ni * 2 + hf;
                const float2 tf = lds64f(rTf + (uint32_t)(pos * 1024));
                float x0 = c1 * tf.x;
                float x1 = c1 * tf.y;
                if ((dm0 >> pos) & 1) x0 += cc0;
                if ((dm1 >> pos) & 1) x1 += cc0;
                acc[ni][2 * hf]     = x0;
                acc[ni][2 * hf + 1] = x1;
            }

        // mm: AC_new = AC*T2 + acc_init, B-frags software-pipelined one ahead.
        // Flattened (ks,nj) loop: iteration it -> ks = it>>2, nj = it&3.
        {
            uint32_t bh[2][4], bl[2][4];
            ldsm4(bh[0], yb[0]);
            ldsm4(bl[0], yb[0] + TILE);
#pragma unroll
            for (int it = 0; it < 16; ++it) {
                const int ks  = it >> 2, nj = it & 3;
                const int cur = it & 1,  nxt = cur ^ 1;
                if (it < 15) {
                    const int it2 = it + 1;
                    const uint32_t ya = yb[it2 >> 2] + (uint32_t)((it2 & 3) * 2048);
                    ldsm4(bh[nxt], ya);
                    ldsm4(bl[nxt], ya + TILE);
                }
                mma_nj(acc, nj, &fh[4 * ks], &fl[4 * ks], bh[cur], bl[cur]);
            }
        }

        if (step < 3) {
            // epilogue = split only
#pragma unroll
            for (int pos = 0; pos < 16; ++pos)
                split_pair(acc[pos >> 1][2 * (pos & 1)],
                           acc[pos >> 1][2 * (pos & 1) + 1], fh[pos], fl[pos]);
        } else {
            // final: store to global
#pragma unroll
            for (int ni = 0; ni < 8; ++ni)
#pragma unroll
                for (int hf = 0; hf < 2; ++hf) {
                    const int gr = row0 + er + hf * 8;
                    const int gc = ni * 8 + ec;
                    float2* gp = reinterpret_cast<float2*>(
                        gout + (size_t)blockIdx.x * 4096 + gr * 64 + gc);
                    *gp = make_float2(acc[ni][2 * hf], acc[ni][2 * hf + 1]);
                }
        }
    }
}

extern "C" void kernel_launch(void* const* d_in, const int* in_sizes, int n_in,
                              void* d_out, int out_size) {
    const float* in = (const float*)d_in[0];
    float* out = (float*)d_out;
    const int nmat = in_sizes[0] / 4096;   // 8192 matrices of 64x64

    // Chebyshev coefficients of log on [1,6], converted to monomial basis.
    Poly P;
    {
        const double alpha = 3.5, beta = 2.5;
        const double r = (alpha - sqrt(alpha * alpha - beta * beta)) / beta;
        double c[DEG + 1];
        c[0] = log(alpha / (1.0 + r * r));
        double rk = 1.0;
        for (int k = 1; k <= DEG; ++k) {
            rk *= r;
            c[k] = ((k & 1) ? 2.0 : -2.0) * rk / (double)k;
        }
        double mono[DEG + 1], Tm1[DEG + 1], Tc[DEG + 1], Tn[DEG + 1];
        for (int j = 0; j <= DEG; ++j) { mono[j] = 0; Tm1[j] = 0; Tc[j] = 0; }
        Tm1[0] = 1.0;            // T0
        Tc[1]  = 1.0;            // T1
        for (int j = 0; j <= DEG; ++j) mono[j] = c[0] * Tm1[j] + c[1] * Tc[j];
        for (int k = 2; k <= DEG; ++k) {
            for (int j = 0; j <= DEG; ++j) {
                double t = -Tm1[j];
                if (j > 0) t += 2.0 * Tc[j - 1];
                Tn[j] = t;
            }
            for (int j = 0; j <= DEG; ++j) {
                mono[j] += c[k] * Tn[j];
                Tm1[j] = Tc[j];
                Tc[j]  = Tn[j];
            }
        }
        for (int j = 0; j <= DEG; ++j) P.a[j] = (float)mono[j];
    }

    cudaFuncSetAttribute(logm_hmma_kernel,
                         cudaFuncAttributeMaxDynamicSharedMemorySize, SMEM_TOT);
    logm_hmma_kernel<<<nmat, 128, SMEM_TOT>>>(in, out, P);
}

// round 17
// speedup vs baseline: 1.9734x; 1.1780x over previous
#include <cuda_runtime.h>
#include <cuda_bf16.h>
#include <cuda_fp16.h>
#include <math.h>
#include <stdint.h>

// Batched log(M) for SPD 64x64 matrices, spectrum in [1, 6]:
// degree-8 Chebyshev poly of log in T = (M - 3.5 I)/2.5, PS s=2 (4 matmuls).
// Step 0 (T2 = T*T): bf16 3-term split products (exact-ish T2), as R13.
// Steps 1-3 (Horner): fp16 asymmetric 2-term — A = fp16 RN pair from
// registers (C-frag == A-frag layout), B = SINGLE fp16 RN T2 tile. Halves
// B-fragment smem traffic and cuts MMA count 96->64 per warp-step; dropped
// AC*(T2 - fp16(T2)) term costs ~1.5e-4/step against a 1e-3 budget.
// One barrier after step 0; steps 1-3 barrier-free; acc preloaded with
// c1*T + cc0*I from a conflict-free fragment-layout f32 buffer. 40KB smem.

constexpr int DEG = 8;
struct Poly { float a[DEG + 1]; };

constexpr int TILE = 8192;            // one 64x64 16-bit tile
constexpr int SMEM_TOT = 5 * TILE;    // Th,Tl | T2 (fp16) | Tfrag f32 (16KB)

__device__ __forceinline__ uint32_t smem_u32(const void* p) {
    uint32_t a;
    asm("{ .reg .u64 t; cvta.to.shared.u64 t, %1; cvt.u32.u64 %0, t; }"
        : "=r"(a) : "l"(p));
    return a;
}
__device__ __forceinline__ void sts32(uint32_t addr, uint32_t v) {
    asm volatile("st.shared.b32 [%0], %1;" :: "r"(addr), "r"(v));
}
__device__ __forceinline__ uint32_t lds32(uint32_t addr) {
    uint32_t v;
    asm volatile("ld.shared.b32 %0, [%1];" : "=r"(v) : "r"(addr));
    return v;
}
__device__ __forceinline__ void sts64(uint32_t addr, float x, float y) {
    asm volatile("st.shared.v2.f32 [%0], {%1,%2};" :: "r"(addr), "f"(x), "f"(y));
}
__device__ __forceinline__ float2 lds64f(uint32_t addr) {
    float2 v;
    asm volatile("ld.shared.v2.f32 {%0,%1}, [%2];" : "=f"(v.x), "=f"(v.y) : "r"(addr));
    return v;
}
__device__ __forceinline__ uint32_t packbf(float lo, float hi) {
    uint32_t r;
    asm("cvt.rn.bf16x2.f32 %0, %1, %2;" : "=r"(r) : "f"(hi), "f"(lo));
    return r;
}
__device__ __forceinline__ float2 unpackbf(uint32_t u) {
    const __nv_bfloat162 b = *reinterpret_cast<const __nv_bfloat162*>(&u);
    return make_float2(__bfloat162float(b.x), __bfloat162float(b.y));
}
// bf16 truncation split (step 0 path, unchanged from R13)
__device__ __forceinline__ void split_pair(float x0, float x1,
                                           uint32_t& h01, uint32_t& l01) {
    const uint32_t u0 = __float_as_uint(x0), u1 = __float_as_uint(x1);
    asm("prmt.b32 %0, %1, %2, 0x7632;" : "=r"(h01) : "r"(u0), "r"(u1));
    const float l0 = x0 - __uint_as_float(u0 & 0xFFFF0000u);
    const float l1 = x1 - __uint_as_float(u1 & 0xFFFF0000u);
    l01 = packbf(l0, l1);
}
// fp16 RN pack (low half = first arg)
__device__ __forceinline__ uint32_t packf16(float lo, float hi) {
    uint32_t r;
    asm("cvt.rn.f16x2.f32 %0, %1, %2;" : "=r"(r) : "f"(hi), "f"(lo));
    return r;
}
// fp16 RN pair split: h = f16x2(x0,x1), l = f16x2(residuals)
__device__ __forceinline__ void split_pair_f16(float x0, float x1,
                                               uint32_t& h01, uint32_t& l01) {
    h01 = packf16(x0, x1);
    float h0, h1;
    asm("{.reg .f16 a,b; mov.b32 {a,b}, %2; cvt.f32.f16 %0, a; cvt.f32.f16 %1, b;}"
        : "=f"(h0), "=f"(h1) : "r"(h01));
    l01 = packf16(x0 - h0, x1 - h1);
}
__device__ __forceinline__ void ldsm4(uint32_t r[4], uint32_t addr) {
    asm volatile("ldmatrix.sync.aligned.m8n8.x4.shared.b16 {%0,%1,%2,%3}, [%4];"
                 : "=r"(r[0]), "=r"(r[1]), "=r"(r[2]), "=r"(r[3]) : "r"(addr));
}
__device__ __forceinline__ void mma16816(float c[4], const uint32_t a[4],
                                         uint32_t b0, uint32_t b1) {
    asm volatile(
        "mma.sync.aligned.m16n8k16.row.col.f32.bf16.bf16.f32 "
        "{%0,%1,%2,%3}, {%4,%5,%6,%7}, {%8,%9}, {%0,%1,%2,%3};"
        : "+f"(c[0]), "+f"(c[1]), "+f"(c[2]), "+f"(c[3])
        : "r"(a[0]), "r"(a[1]), "r"(a[2]), "r"(a[3]), "r"(b0), "r"(b1));
}
__device__ __forceinline__ void mma16816h(float c[4], const uint32_t a[4],
                                          uint32_t b0, uint32_t b1) {
    asm volatile(
        "mma.sync.aligned.m16n8k16.row.col.f32.f16.f16.f32 "
        "{%0,%1,%2,%3}, {%4,%5,%6,%7}, {%8,%9}, {%0,%1,%2,%3};"
        : "+f"(c[0]), "+f"(c[1]), "+f"(c[2]), "+f"(c[3])
        : "r"(a[0]), "r"(a[1]), "r"(a[2]), "r"(a[3]), "r"(b0), "r"(b1));
}

// step-0: 6 bf16 MMAs for one n16 group (3 split terms x 2 n8 subs)
__device__ __forceinline__ void mma_nj(float acc[8][4], int nj,
                                       const uint32_t ah[4], const uint32_t al[4],
                                       const uint32_t bh[4], const uint32_t bl[4]) {
#pragma unroll
    for (int sub = 0; sub < 2; ++sub) {
        float* c = acc[nj * 2 + sub];
        mma16816(c, ah, bh[sub], bh[sub + 2]);   // Ah*Bh
        mma16816(c, ah, bl[sub], bl[sub + 2]);   // Ah*Bl
        mma16816(c, al, bh[sub], bh[sub + 2]);   // Al*Bh
    }
}
// step-0 k16 chunk (bf16 3-term, B from smem)
__device__ __forceinline__ void mma_k16(float acc[8][4],
                                        const uint32_t ah[4], const uint32_t al[4],
                                        uint32_t ybase) {
#pragma unroll
    for (int nj = 0; nj < 4; ++nj) {
        uint32_t bh[4], bl[4];
        ldsm4(bh, ybase + nj * 2048);
        ldsm4(bl, ybase + nj * 2048 + TILE);
        mma_nj(acc, nj, ah, al, bh, bl);
    }
}
// steps 1-3 k16 chunk (fp16 2-term, single-B from smem)
__device__ __forceinline__ void mma_k16h(float acc[8][4],
                                         const uint32_t ah[4], const uint32_t al[4],
                                         uint32_t ybase) {
#pragma unroll
    for (int nj = 0; nj < 4; ++nj) {
        uint32_t bh[4];
        ldsm4(bh, ybase + nj * 2048);
#pragma unroll
        for (int sub = 0; sub < 2; ++sub) {
            float* c = acc[nj * 2 + sub];
            mma16816h(c, ah, bh[sub], bh[sub + 2]);   // Ah*B
            mma16816h(c, al, bh[sub], bh[sub + 2]);   // Al*B
        }
    }
}

__global__ __launch_bounds__(128, 4)
void logm_hmma_kernel(const float* __restrict__ gin,
                      float* __restrict__ gout,
                      Poly P) {
    extern __shared__ char smc[];
    const uint32_t sb  = smem_u32(smc);
    const uint32_t bT  = sb;              // T bf16 hi (+TILE lo), persistent
    const uint32_t bT2 = sb + 2 * TILE;   // T2 fp16 (single tile)
    const uint32_t bTf = sb + 3 * TILE;   // T f32 fragment layout [pos][tid]

    const int tid  = threadIdx.x;
    const int warp = tid >> 5;
    const int lane = tid & 31;
    const int row0 = warp * 16;

    // ---- prologue: T = (M - 3.5 I)/2.5; truncation-split into bT
    {
        const int pr = tid >> 1, ph = tid & 1;
        const float* gp = gin + (size_t)blockIdx.x * 4096 + pr * 64 + ph * 32;
        float v[32];
#pragma unroll
        for (int j = 0; j < 32; j += 4) {
            const float4 t4 = *reinterpret_cast<const float4*>(gp + j);
            v[j] = t4.x; v[j + 1] = t4.y; v[j + 2] = t4.z; v[j + 3] = t4.w;
        }
        const float inv_beta = 1.0f / 2.5f, alpha = 3.5f;
#pragma unroll
        for (int j = 0; j < 32; ++j)
            v[j] = (v[j] - ((ph * 32 + j == pr) ? alpha : 0.0f)) * inv_beta;

        const uint32_t pmsk = (uint32_t)((pr & 7) << 4);
#pragma unroll
        for (int j = 0; j < 16; ++j) {
            const uint32_t off = ((uint32_t)(pr * 128 + ph * 64 + 4 * j)) ^ pmsk;
            uint32_t h01, l01;
            split_pair(v[2 * j], v[2 * j + 1], h01, l01);
            sts32(bT + off, h01);
            sts32(bT + TILE + off, l01);
        }
    }
    __syncthreads();

    // ---- per-thread constant geometry
    const int la = lane & 15, lc = lane >> 4;
    const uint32_t msk = (uint32_t)((la & 7) << 4);
    const uint32_t rA  = (uint32_t)((row0 + la) * 128 + lc * 16);
    const uint32_t rY  = (uint32_t)(la * 128 + lc * 16);
    const int er = lane >> 2, ec = (lane & 3) * 2;
    const uint32_t mskE = (uint32_t)(er << 4);
    const uint32_t rE0  = (uint32_t)((row0 + er) * 128 + ec * 2);
    const uint32_t rTf  = bTf + (uint32_t)(tid * 8);   // own fragment column

    // diag masks over pos = ni*2+hf
    uint32_t dm0 = 0, dm1 = 0;
#pragma unroll
    for (int ni = 0; ni < 8; ++ni)
#pragma unroll
        for (int hf = 0; hf < 2; ++hf) {
            const int gr = row0 + er + hf * 8;
            const int gc = ni * 8 + ec;
            if (gr == gc)     dm0 |= 1u << (ni * 2 + hf);
            if (gr == gc + 1) dm1 |= 1u << (ni * 2 + hf);
        }

    // ---- one-time gather: T fragments -> bTf[pos][tid] (thread-private slots)
#pragma unroll
    for (int ni = 0; ni < 8; ++ni)
#pragma unroll
        for (int hf = 0; hf < 2; ++hf) {
            const uint32_t rel = (rE0 + (uint32_t)(ni * 16 + hf * 1024)) ^ mskE;
            const float2 th = unpackbf(lds32(bT + rel));
            const float2 tl = unpackbf(lds32(bT + TILE + rel));
            sts64(rTf + (uint32_t)((ni * 2 + hf) * 1024), th.x + tl.x, th.y + tl.y);
        }

    float    acc[8][4];
    uint32_t fh[16], fl[16];   // fp16 A-fragments of own AC rows (pos = ni*2+hf)

    // ================= step 0: X = Y = T, bf16 3-term (exact R13) ===========
#pragma unroll
    for (int t = 0; t < 8; ++t)
#pragma unroll
        for (int e = 0; e < 4; ++e) acc[t][e] = 0.0f;
#pragma unroll
    for (int ks = 0; ks < 4; ++ks) {
        const uint32_t kb = (uint32_t)(ks * 32);
        const uint32_t xa = bT + ((rA + kb) ^ msk);
        uint32_t ah[4], al[4];
        ldsm4(ah, xa);
        ldsm4(al, xa + TILE);
        mma_k16(acc, ah, al, bT + ((rY + kb) ^ msk));
    }
    // epilogue 0: T2 = fp16 RN(D) -> bT2 (single tile); AC0 -> fp16 pair frags
    {
        const float cd = P.a[8], c1 = P.a[7], cc0 = P.a[6];
#pragma unroll
        for (int ni = 0; ni < 8; ++ni)
#pragma unroll
            for (int hf = 0; hf < 2; ++hf) {
                const int pos = ni * 2 + hf;
                const uint32_t rel = (rE0 + (uint32_t)(ni * 16 + hf * 1024)) ^ mskE;
                const float d0 = acc[ni][2 * hf];
                const float d1 = acc[ni][2 * hf + 1];
                sts32(bT2 + rel, packf16(d0, d1));       // B for steps 1-3
                const float2 tf = lds64f(rTf + (uint32_t)(pos * 1024));
                float x0 = cd * d0 + c1 * tf.x;
                float x1 = cd * d1 + c1 * tf.y;
                if ((dm0 >> pos) & 1) x0 += cc0;
                if ((dm1 >> pos) & 1) x1 += cc0;
                split_pair_f16(x0, x1, fh[pos], fl[pos]);
            }
    }
    __syncthreads();   // T2 visible; steps 1-3 barrier-free

    // precomputed swizzled T2 chunk bases (reused by all 3 remaining steps)
    uint32_t yb[4];
#pragma unroll
    for (int ks = 0; ks < 4; ++ks)
        yb[ks] = bT2 + ((rY + (uint32_t)(ks * 32)) ^ msk);

    // ================= steps 1..3: fp16 2-term, acc preloaded ==============
#pragma unroll
    for (int step = 1; step < 4; ++step) {
        const float c1  = (step == 1) ? P.a[5] : (step == 2) ? P.a[3] : P.a[1];
        const float cc0 = (step == 1) ? P.a[4] : (step == 2) ? P.a[2] : P.a[0];

        // init acc = c1*T + cc0*I  (conflict-free LDS.64 from own fragment col)
#pragma unroll
        for (int ni = 0; ni < 8; ++ni)
#pragma unroll
            for (int hf = 0; hf < 2; ++hf) {
                const int pos = ni * 2 + hf;
                const float2 tf = lds64f(rTf + (uint32_t)(pos * 1024));
                float x0 = c1 * tf.x;
                float x1 = c1 * tf.y;
                if ((dm0 >> pos) & 1) x0 += cc0;
                if ((dm1 >> pos) & 1) x1 += cc0;
                acc[ni][2 * hf]     = x0;
                acc[ni][2 * hf + 1] = x1;
            }

        // mm: AC_new = AC*T2 + acc_init  (A-frags from registers, single-B)
#pragma unroll
        for (int ks = 0; ks < 4; ++ks)
            mma_k16h(acc, &fh[4 * ks], &fl[4 * ks], yb[ks]);

        if (step < 3) {
            // epilogue = fp16 pair split only
#pragma unroll
            for (int pos = 0; pos < 16; ++pos)
                split_pair_f16(acc[pos >> 1][2 * (pos & 1)],
                               acc[pos >> 1][2 * (pos & 1) + 1], fh[pos], fl[pos]);
        } else {
            // final: store to global
#pragma unroll
            for (int ni = 0; ni < 8; ++ni)
#pragma unroll
                for (int hf = 0; hf < 2; ++hf) {
                    const int gr = row0 + er + hf * 8;
                    const int gc = ni * 8 + ec;
                    float2* gp = reinterpret_cast<float2*>(
                        gout + (size_t)blockIdx.x * 4096 + gr * 64 + gc);
                    *gp = make_float2(acc[ni][2 * hf], acc[ni][2 * hf + 1]);
                }
        }
    }
}

extern "C" void kernel_launch(void* const* d_in, const int* in_sizes, int n_in,
                              void* d_out, int out_size) {
    const float* in = (const float*)d_in[0];
    float* out = (float*)d_out;
    const int nmat = in_sizes[0] / 4096;   // 8192 matrices of 64x64

    // Chebyshev coefficients of log on [1,6], converted to monomial basis.
    Poly P;
    {
        const double alpha = 3.5, beta = 2.5;
        const double r = (alpha - sqrt(alpha * alpha - beta * beta)) / beta;
        double c[DEG + 1];
        c[0] = log(alpha / (1.0 + r * r));
        double rk = 1.0;
        for (int k = 1; k <= DEG; ++k) {
            rk *= r;
            c[k] = ((k & 1) ? 2.0 : -2.0) * rk / (double)k;
        }
        double mono[DEG + 1], Tm1[DEG + 1], Tc[DEG + 1], Tn[DEG + 1];
        for (int j = 0; j <= DEG; ++j) { mono[j] = 0; Tm1[j] = 0; Tc[j] = 0; }
        Tm1[0] = 1.0;            // T0
        Tc[1]  = 1.0;            // T1
        for (int j = 0; j <= DEG; ++j) mono[j] = c[0] * Tm1[j] + c[1] * Tc[j];
        for (int k = 2; k <= DEG; ++k) {
            for (int j = 0; j <= DEG; ++j) {
                double t = -Tm1[j];
                if (j > 0) t += 2.0 * Tc[j - 1];
                Tn[j] = t;
            }
            for (int j = 0; j <= DEG; ++j) {
                mono[j] += c[k] * Tn[j];
                Tm1[j] = Tc[j];
                Tc[j]  = Tn[j];
            }
        }
        for (int j = 0; j <= DEG; ++j) P.a[j] = (float)mono[j];
    }

    cudaFuncSetAttribute(logm_hmma_kernel,
                         cudaFuncAttributeMaxDynamicSharedMemorySize, SMEM_TOT);
    logm_hmma_kernel<<<nmat, 128, SMEM_TOT>>>(in, out, P);
}